// round 1
// baseline (speedup 1.0000x reference)
#include <cuda_runtime.h>
#include <cstdint>
#include <cstddef>

// ---- static problem sizes (match reference) ----
#define Bg 128
#define Nn 256
#define Dd 128
#define Kk 16
#define Mm 16
#define CG_ITERS 10
#define SINK_ITERS 50
#define CAP 128          // max unique neighbors per row (mean ~16, P(>128) ~ 0)
#define STR 20           // smem staging stride in floats (80B, 16B-aligned)

// ---- device scratch (static allocation only; no cudaMalloc) ----
__device__ float           g_C[(size_t)Bg * Nn * Nn];      // dense adjacency counts (33.5MB)
__device__ float           g_val[(size_t)Bg * Nn * CAP];   // CSR values (counts)
__device__ unsigned short  g_col[(size_t)Bg * Nn * CAP];   // CSR cols (within graph)
__device__ int             g_cnt[Bg * Nn];                 // CSR row lengths
__device__ float           g_cc1[Bg * Nn];                 // (C1^2 @ p)_i = sum_j C_ij^2 / N

// ============================ precompute ============================

__global__ void k_zero()
{
    size_t n = (size_t)Bg * Nn * Nn;
    for (size_t i = (size_t)blockIdx.x * blockDim.x + threadIdx.x; i < n;
         i += (size_t)gridDim.x * blockDim.x)
        g_C[i] = 0.f;
}

__global__ void k_scatter(const int* __restrict__ ei, int E)
{
    int e = blockIdx.x * blockDim.x + threadIdx.x;
    if (e >= E) return;
    int s = ei[e];
    int t = ei[E + e];
    int g = s >> 8;                       // graph id (N=256)
    // exact integer counting in float: order-independent, deterministic
    atomicAdd(&g_C[((size_t)(g * Nn + (s & 255))) * Nn + (t & 255)], 1.f);
}

// one warp per row: deterministic ballot-compaction into CSR + sum of squares
__global__ void k_csr()
{
    int w = (blockIdx.x * blockDim.x + threadIdx.x) >> 5;
    int lane = threadIdx.x & 31;
    if (w >= Bg * Nn) return;
    const float* Crow = g_C + (size_t)w * Nn;
    float s2 = 0.f;
    int out = 0;
    size_t base = (size_t)w * CAP;
    for (int c0 = 0; c0 < Nn; c0 += 32) {
        float v = Crow[c0 + lane];
        s2 += v * v;
        unsigned m = __ballot_sync(0xffffffffu, v != 0.f);
        int off = __popc(m & ((1u << lane) - 1u));
        if (v != 0.f && (out + off) < CAP) {
            g_val[base + out + off] = v;
            g_col[base + out + off] = (unsigned short)(c0 + lane);
        }
        out += __popc(m);
    }
    #pragma unroll
    for (int o = 16; o; o >>= 1) s2 += __shfl_xor_sync(0xffffffffu, s2, o);
    if (lane == 0) {
        g_cnt[w] = out > CAP ? CAP : out;
        g_cc1[w] = s2 * (1.f / Nn);
    }
}

// ============================ main kernel ============================

__device__ __forceinline__ float ex2(float x)
{
    float r; asm("ex2.approx.ftz.f32 %0, %1;" : "=f"(r) : "f"(x)); return r;
}
__device__ __forceinline__ float lg2(float x)
{
    float r; asm("lg2.approx.ftz.f32 %0, %1;" : "=f"(r) : "f"(x)); return r;
}

// sparse row gather: R[i][:] = sum_entries val * Tstage[col][:]
__device__ __forceinline__ void spmm_row(const float* sT, size_t cbase, int cnt,
                                         float R[16])
{
    #pragma unroll
    for (int j = 0; j < 16; j++) R[j] = 0.f;
    for (int e = 0; e < cnt; e++) {
        int   c  = g_col[cbase + e];
        float vv = g_val[cbase + e];
        const float4* tp = (const float4*)(sT + c * STR);
        float4 t0 = tp[0], t1 = tp[1], t2 = tp[2], t3 = tp[3];
        R[0]  += vv * t0.x; R[1]  += vv * t0.y; R[2]  += vv * t0.z; R[3]  += vv * t0.w;
        R[4]  += vv * t1.x; R[5]  += vv * t1.y; R[6]  += vv * t1.z; R[7]  += vv * t1.w;
        R[8]  += vv * t2.x; R[9]  += vv * t2.y; R[10] += vv * t2.z; R[11] += vv * t2.w;
        R[12] += vv * t3.x; R[13] += vv * t3.y; R[14] += vv * t3.z; R[15] += vv * t3.w;
    }
}

__global__ __launch_bounds__(256, 2)
void k_fgw(const float* __restrict__ x,
           const float* __restrict__ tA,
           const float* __restrict__ tF,
           const float* __restrict__ q0,
           const float* __restrict__ a0,
           float* __restrict__ out)
{
    __shared__ __align__(16) float sT[Nn * STR];   // staging (also feature buffer at init)
    __shared__ __align__(16) float sC2[Mm * Mm];
    __shared__ float scc2[Mm];     // (C2^2 @ q)_j
    __shared__ float sG[Mm];       // Sinkhorn G (log2 domain)
    __shared__ float sMx[Mm];      // column max
    __shared__ float sP[Mm * 16];  // partial max
    __shared__ float sP2[Mm * 16]; // partial sum
    __shared__ float slogq2[Mm];
    __shared__ float sq[Mm];
    __shared__ float sFn[Mm];      // template feature norms
    __shared__ float sred[8 * 4];
    __shared__ float sScal[4];

    const int tid  = threadIdx.x;
    const int bid  = blockIdx.x;
    const int b    = bid >> 4;
    const int k    = bid & 15;
    const int lane = tid & 31;
    const int wid  = tid >> 5;
    const float L2E = 1.44269504088896340736f;
    const float LOGP2 = -8.0f;                     // log2(1/256)

    const float alpha = 1.f / (1.f + expf(-a0[0]));

    // --- load C2, q softmax, features ---
    sC2[tid] = tA[k * 256 + tid];
    if (tid == 0) {
        float qv[16], mq = -1e30f;
        #pragma unroll
        for (int j = 0; j < 16; j++) { qv[j] = q0[k * 16 + j]; mq = fmaxf(mq, qv[j]); }
        float s = 0.f;
        #pragma unroll
        for (int j = 0; j < 16; j++) { qv[j] = ex2((qv[j] - mq) * L2E); s += qv[j]; }
        float inv = 1.f / s;
        #pragma unroll
        for (int j = 0; j < 16; j++) {
            float qq = qv[j] * inv;
            sq[j] = qq;
            slogq2[j] = lg2(qq);
        }
    }
    for (int t = tid; t < Mm * Dd; t += 256) sT[t] = tF[k * Mm * Dd + t];
    __syncthreads();

    // --- constC2_j, feature norms (threads <16) ---
    if (tid < 16) {
        float s = 0.f;
        #pragma unroll
        for (int l = 0; l < 16; l++) { float c = sC2[tid * 16 + l]; s += c * c * sq[l]; }
        scc2[tid] = s;
        float fn = 0.f;
        for (int d = 0; d < Dd; d++) { float f = sT[tid * Dd + d]; fn += f * f; }
        sFn[tid] = fn;
    }

    // --- Mcost row: M[j] = |x_i|^2 + |f_j|^2 - 2 x_i . f_j ---
    float Mr[16];
    #pragma unroll
    for (int j = 0; j < 16; j++) Mr[j] = 0.f;
    float xn = 0.f;
    const float4* xr = (const float4*)(x + ((size_t)(b * Nn + tid)) * Dd);
    for (int d4 = 0; d4 < Dd / 4; d4++) {
        float4 xv = xr[d4];
        xn += xv.x * xv.x + xv.y * xv.y + xv.z * xv.z + xv.w * xv.w;
        #pragma unroll
        for (int j = 0; j < 16; j++) {
            float4 fv = ((const float4*)sT)[j * (Dd / 4) + d4];
            Mr[j] += xv.x * fv.x + xv.y * fv.y + xv.z * fv.z + xv.w * fv.w;
        }
    }
    __syncthreads();   // sFn ready, sT feature reads done
    #pragma unroll
    for (int j = 0; j < 16; j++) Mr[j] = xn + sFn[j] - 2.f * Mr[j];

    // --- CSR row info ---
    const int grow = b * Nn + tid;
    const int cnt = g_cnt[grow];
    const size_t cbase = (size_t)grow * CAP;
    const float cc1 = g_cc1[grow];

    // --- T0 = p q^T ---
    float T[16];
    #pragma unroll
    for (int j = 0; j < 16; j++) T[j] = sq[j] * (1.f / Nn);

    float CTC[16];
    const int cj = tid >> 4, cs = tid & 15;

    for (int it = 0; it <= CG_ITERS; it++) {
        // ===== CTC = C1 @ T @ C2^T =====
        {
            float4* st = (float4*)(sT + tid * STR);
            st[0] = make_float4(T[0], T[1], T[2], T[3]);
            st[1] = make_float4(T[4], T[5], T[6], T[7]);
            st[2] = make_float4(T[8], T[9], T[10], T[11]);
            st[3] = make_float4(T[12], T[13], T[14], T[15]);
        }
        __syncthreads();
        float R[16];
        spmm_row(sT, cbase, cnt, R);
        __syncthreads();
        #pragma unroll
        for (int jj = 0; jj < 16; jj++) {
            float s = 0.f;
            #pragma unroll
            for (int l4 = 0; l4 < 4; l4++) {
                float4 c4 = ((const float4*)sC2)[jj * 4 + l4];
                s += R[l4 * 4 + 0] * c4.x + R[l4 * 4 + 1] * c4.y
                   + R[l4 * 4 + 2] * c4.z + R[l4 * 4 + 3] * c4.w;
            }
            CTC[jj] = s;
        }
        if (it == CG_ITERS) break;   // final CTC only (for gw value)

        // ===== grad, reg scale =====
        float negC2[16];
        float mxa = 0.f;
        #pragma unroll
        for (int j = 0; j < 16; j++) {
            float g = (1.f - alpha) * Mr[j]
                    + 2.f * alpha * (cc1 + scc2[j] - 2.f * CTC[j]);
            negC2[j] = g;
            mxa = fmaxf(mxa, fabsf(g));
        }
        #pragma unroll
        for (int o = 16; o; o >>= 1) mxa = fmaxf(mxa, __shfl_xor_sync(0xffffffffu, mxa, o));
        if (lane == 0) sred[wid] = mxa;
        __syncthreads();
        if (tid == 0) {
            float m = sred[0];
            #pragma unroll
            for (int w = 1; w < 8; w++) m = fmaxf(m, sred[w]);
            sScal[0] = m;
        }
        if (tid < 16) sG[tid] = 0.f;
        __syncthreads();
        {
            float cscale = -L2E / (0.01f * sScal[0] + 1e-12f);
            #pragma unroll
            for (int j = 0; j < 16; j++) negC2[j] *= cscale;
        }

        // ===== Sinkhorn (log2 domain) =====
        float F2 = 0.f;
        for (int sk = 0; sk < SINK_ITERS; sk++) {
            // F update (row-local)
            float m = -1e30f, t[16];
            #pragma unroll
            for (int j = 0; j < 16; j++) { t[j] = negC2[j] + sG[j]; m = fmaxf(m, t[j]); }
            float s = 0.f;
            #pragma unroll
            for (int j = 0; j < 16; j++) s += ex2(t[j] - m);
            F2 = LOGP2 - (m + lg2(s));
            // stage v = negC2 + F2
            {
                float4* st = (float4*)(sT + tid * STR);
                st[0] = make_float4(negC2[0] + F2, negC2[1] + F2, negC2[2] + F2, negC2[3] + F2);
                st[1] = make_float4(negC2[4] + F2, negC2[5] + F2, negC2[6] + F2, negC2[7] + F2);
                st[2] = make_float4(negC2[8] + F2, negC2[9] + F2, negC2[10] + F2, negC2[11] + F2);
                st[3] = make_float4(negC2[12] + F2, negC2[13] + F2, negC2[14] + F2, negC2[15] + F2);
            }
            __syncthreads();
            // column phase: thread (cj, cs) handles rows cs, cs+16, ...
            float v[16], cm = -1e30f;
            #pragma unroll
            for (int r = 0; r < 16; r++) {
                v[r] = sT[(cs + (r << 4)) * STR + cj];
                cm = fmaxf(cm, v[r]);
            }
            sP[cj * 16 + cs] = cm;
            __syncthreads();
            if (tid < 16) {
                float m2 = sP[tid * 16];
                #pragma unroll
                for (int r = 1; r < 16; r++) m2 = fmaxf(m2, sP[tid * 16 + r]);
                sMx[tid] = m2;
            }
            __syncthreads();
            float M2 = sMx[cj], ss = 0.f;
            #pragma unroll
            for (int r = 0; r < 16; r++) ss += ex2(v[r] - M2);
            sP2[cj * 16 + cs] = ss;
            __syncthreads();
            if (tid < 16) {
                float s2 = sP2[tid * 16];
                #pragma unroll
                for (int r = 1; r < 16; r++) s2 += sP2[tid * 16 + r];
                sG[tid] = slogq2[tid] - (sMx[tid] + lg2(s2));
            }
            __syncthreads();
        }

        // ===== Tnew, dT =====
        float dT[16];
        #pragma unroll
        for (int j = 0; j < 16; j++) {
            float tn = ex2(negC2[j] + F2 + sG[j]);
            dT[j] = tn - T[j];
        }

        // ===== D = C1 @ dT @ C2^T =====
        {
            float4* st = (float4*)(sT + tid * STR);
            st[0] = make_float4(dT[0], dT[1], dT[2], dT[3]);
            st[1] = make_float4(dT[4], dT[5], dT[6], dT[7]);
            st[2] = make_float4(dT[8], dT[9], dT[10], dT[11]);
            st[3] = make_float4(dT[12], dT[13], dT[14], dT[15]);
        }
        __syncthreads();
        float Rd[16];
        spmm_row(sT, cbase, cnt, Rd);
        __syncthreads();
        float D[16];
        #pragma unroll
        for (int jj = 0; jj < 16; jj++) {
            float s = 0.f;
            #pragma unroll
            for (int l4 = 0; l4 < 4; l4++) {
                float4 c4 = ((const float4*)sC2)[jj * 4 + l4];
                s += Rd[l4 * 4 + 0] * c4.x + Rd[l4 * 4 + 1] * c4.y
                   + Rd[l4 * 4 + 2] * c4.z + Rd[l4 * 4 + 3] * c4.w;
            }
            D[jj] = s;
        }

        // ===== line search sums =====
        float pa = 0.f, pb1 = 0.f, pb2 = 0.f, pb3 = 0.f;
        #pragma unroll
        for (int j = 0; j < 16; j++) {
            pa  += D[j] * dT[j];
            pb1 += Mr[j] * dT[j];
            pb2 += D[j] * T[j];
            pb3 += CTC[j] * dT[j];
        }
        #pragma unroll
        for (int o = 16; o; o >>= 1) {
            pa  += __shfl_xor_sync(0xffffffffu, pa, o);
            pb1 += __shfl_xor_sync(0xffffffffu, pb1, o);
            pb2 += __shfl_xor_sync(0xffffffffu, pb2, o);
            pb3 += __shfl_xor_sync(0xffffffffu, pb3, o);
        }
        if (lane == 0) {
            sred[wid * 4 + 0] = pa;  sred[wid * 4 + 1] = pb1;
            sred[wid * 4 + 2] = pb2; sred[wid * 4 + 3] = pb3;
        }
        __syncthreads();
        if (tid == 0) {
            float Sa = 0.f, S1 = 0.f, S2 = 0.f, S3 = 0.f;
            #pragma unroll
            for (int w = 0; w < 8; w++) {
                Sa += sred[w * 4 + 0]; S1 += sred[w * 4 + 1];
                S2 += sred[w * 4 + 2]; S3 += sred[w * 4 + 3];
            }
            float A  = -2.f * alpha * Sa;
            float Bc = (1.f - alpha) * S1 - 2.f * alpha * (S2 + S3);
            float tstep;
            if (A > 0.f) {
                tstep = -Bc / (2.f * A + 1e-16f);
                tstep = fminf(1.f, fmaxf(0.f, tstep));
            } else {
                tstep = (A + Bc < 0.f) ? 1.f : 0.f;
            }
            sScal[1] = tstep;
        }
        __syncthreads();
        float ts = sScal[1];
        #pragma unroll
        for (int j = 0; j < 16; j++) T[j] += ts * dT[j];
    }

    // ===== epilogue: gw + lin =====
    float pg = 0.f, pl = 0.f;
    #pragma unroll
    for (int j = 0; j < 16; j++) {
        pg += (cc1 + scc2[j] - 2.f * CTC[j]) * T[j];
        pl += Mr[j] * T[j];
    }
    #pragma unroll
    for (int o = 16; o; o >>= 1) {
        pg += __shfl_xor_sync(0xffffffffu, pg, o);
        pl += __shfl_xor_sync(0xffffffffu, pl, o);
    }
    if (lane == 0) { sred[wid * 2] = pg; sred[wid * 2 + 1] = pl; }
    __syncthreads();
    if (tid == 0) {
        float Gw = 0.f, L = 0.f;
        #pragma unroll
        for (int w = 0; w < 8; w++) { Gw += sred[w * 2]; L += sred[w * 2 + 1]; }
        out[bid] = (1.f - alpha) * L + alpha * Gw;
    }
}

// ============================ launch ============================

extern "C" void kernel_launch(void* const* d_in, const int* in_sizes, int n_in,
                              void* d_out, int out_size)
{
    const float* x  = (const float*)d_in[0];
    const int*   ei = (const int*)  d_in[1];
    // d_in[2] = batch (unused; graphs are equal-size blocks)
    const float* tA = (const float*)d_in[3];
    const float* tF = (const float*)d_in[4];
    const float* q0 = (const float*)d_in[5];
    const float* a0 = (const float*)d_in[6];
    int E = in_sizes[1] / 2;

    k_zero<<<8192, 256>>>();
    k_scatter<<<(E + 255) / 256, 256>>>(ei, E);
    k_csr<<<(Bg * Nn * 32 + 255) / 256, 256>>>();
    k_fgw<<<Bg * Kk, 256>>>(x, tA, tF, q0, a0, (float*)d_out);
}